// round 1
// baseline (speedup 1.0000x reference)
#include <cuda_runtime.h>

#define NN   50000
#define NE   800000
#define ET   (NE + NN)        // 850000 edges incl self-loops
#define INC  128
#define HID  32
#define H1   8
#define D1   256              // H1*HID
#define D2   64

#define ENC_NEGINF 0x007FFFFFu   // fenc(-inf)

__device__ __forceinline__ unsigned fenc(float f) {
    unsigned u = __float_as_uint(f);
    return (u & 0x80000000u) ? ~u : (u | 0x80000000u);
}
__device__ __forceinline__ float fdec(unsigned u) {
    return __uint_as_float((u & 0x80000000u) ? (u & 0x7FFFFFFFu) : ~u);
}
__device__ __forceinline__ float lrelu(float v) { return v > 0.f ? v : 0.2f * v; }

// ---- scratch (static device globals; no allocation allowed) ----
__device__ float    g_h1[(size_t)NN * D1];     // x @ W1            [N,256]
__device__ float    g_out1[(size_t)NN * D1];   // layer1 accum / relu'd input to L2
__device__ float    g_as1[NN * H1];
__device__ float    g_ad1[NN * H1];
__device__ unsigned g_m1[NN * H1];
__device__ float    g_den1[NN * H1];
__device__ float    g_e1[(size_t)ET * H1];     // edge logits layer1 [E,H]

__device__ float    g_h2[(size_t)NN * D2];     // h_relu @ W2       [N,64]
__device__ float    g_as2[NN];
__device__ float    g_ad2[NN];
__device__ unsigned g_m2[NN];
__device__ float    g_den2[NN];
__device__ float    g_e2[ET];

// ============================================================
// Simple register-tiled SGEMM: C[M,N] = A[M,K] * B[K,N]
// BM=BN=64, BK=16, 256 threads, 4x4 microtile
// ============================================================
__global__ void sgemm(const float* __restrict__ A, const float* __restrict__ B,
                      float* __restrict__ C, int M, int N, int K) {
    const int BM = 64, BN = 64, BK = 16;
    __shared__ float As[BK][BM + 4];
    __shared__ float Bs[BK][BN + 4];
    int t  = threadIdx.x;          // 0..255
    int tx = t & 15, ty = t >> 4;
    int row0 = blockIdx.y * BM, col0 = blockIdx.x * BN;
    float acc[4][4] = {};

    for (int kt = 0; kt < K; kt += BK) {
#pragma unroll
        for (int i = 0; i < 4; i++) {
            int idx = t + i * 256;             // 64x16 A tile
            int r = idx >> 4, k = idx & 15;
            int gr = row0 + r;
            As[k][r] = (gr < M) ? A[(size_t)gr * K + kt + k] : 0.f;
        }
#pragma unroll
        for (int i = 0; i < 4; i++) {
            int idx = t + i * 256;             // 16x64 B tile
            int k = idx >> 6, c = idx & 63;
            Bs[k][c] = B[(size_t)(kt + k) * N + col0 + c];
        }
        __syncthreads();
#pragma unroll
        for (int k = 0; k < BK; k++) {
            float4 a4 = *(const float4*)&As[k][ty * 4];
            float4 b4 = *(const float4*)&Bs[k][tx * 4];
            float ar[4] = {a4.x, a4.y, a4.z, a4.w};
            float br[4] = {b4.x, b4.y, b4.z, b4.w};
#pragma unroll
            for (int i = 0; i < 4; i++)
#pragma unroll
                for (int j = 0; j < 4; j++) acc[i][j] += ar[i] * br[j];
        }
        __syncthreads();
    }
#pragma unroll
    for (int i = 0; i < 4; i++) {
        int gr = row0 + ty * 4 + i;
        if (gr < M) {
            float4 v = {acc[i][0], acc[i][1], acc[i][2], acc[i][3]};
            *(float4*)&C[(size_t)gr * N + col0 + tx * 4] = v;
        }
    }
}

// per-(node,head) attention dot products: as[i] = h[i,:]·att_s[h], ad likewise
__global__ void attn_scores(const float* __restrict__ h,
                            const float* __restrict__ atts,
                            const float* __restrict__ attd,
                            float* __restrict__ as_, float* __restrict__ ad_,
                            int total, int H, int C) {
    int i = blockIdx.x * blockDim.x + threadIdx.x;
    if (i >= total) return;
    int hh = i % H;
    const float4* hv = (const float4*)(h + (size_t)i * C);
    const float4* sv = (const float4*)(atts + (size_t)hh * C);
    const float4* dv = (const float4*)(attd + (size_t)hh * C);
    float s = 0.f, d = 0.f;
    for (int c = 0; c < C / 4; c++) {
        float4 x = hv[c], a = sv[c], b = dv[c];
        s += x.x * a.x + x.y * a.y + x.z * a.z + x.w * a.w;
        d += x.x * b.x + x.y * b.y + x.z * b.z + x.w * b.w;
    }
    as_[i] = s;
    ad_[i] = d;
}

__global__ void init_l1() {
    size_t i = blockIdx.x * (size_t)blockDim.x + threadIdx.x;
    size_t stride = (size_t)gridDim.x * blockDim.x;
    for (size_t j = i; j < (size_t)NN * D1; j += stride) g_out1[j] = 0.f;
    for (size_t j = i; j < (size_t)NN * H1; j += stride) {
        g_den1[j] = 0.f;
        g_m1[j]   = ENC_NEGINF;
    }
}

__global__ void init_l2(float* __restrict__ out) {
    size_t i = blockIdx.x * (size_t)blockDim.x + threadIdx.x;
    size_t stride = (size_t)gridDim.x * blockDim.x;
    for (size_t j = i; j < (size_t)NN * D2; j += stride) out[j] = 0.f;
    for (size_t j = i; j < (size_t)NN; j += stride) {
        g_den2[j] = 0.f;
        g_m2[j]   = ENC_NEGINF;
    }
}

// layer1 edge logits + segment max (thread per edge-head)
__global__ void edge_logits1(const int* __restrict__ ei) {
    int idx = blockIdx.x * blockDim.x + threadIdx.x;
    if (idx >= ET * H1) return;
    int e = idx >> 3, h = idx & 7;
    int s, d;
    if (e < NE) { s = ei[e]; d = ei[NE + e]; } else { s = e - NE; d = s; }
    float v = lrelu(g_as1[s * H1 + h] + g_ad1[d * H1 + h]);
    g_e1[idx] = v;
    atomicMax(&g_m1[d * H1 + h], fenc(v));
}

// layer1 edge accumulation: warp per edge; lane c covers 8 floats (head = lane/4)
__global__ void edge_accum1(const int* __restrict__ ei) {
    int gw   = (blockIdx.x * blockDim.x + threadIdx.x) >> 5;
    int lane = threadIdx.x & 31;
    if (gw >= ET) return;
    int s, d;
    if (gw < NE) { s = ei[gw]; d = ei[NE + gw]; } else { s = gw - NE; d = s; }
    float ex = 0.f;
    if (lane < H1) {
        float v = g_e1[(size_t)gw * H1 + lane];
        float m = fdec(g_m1[d * H1 + lane]);
        ex = __expf(v - m);
        atomicAdd(&g_den1[d * H1 + lane], ex);
    }
    float exh = __shfl_sync(0xffffffffu, ex, lane >> 2);  // head = lane/4
    const float4* hs = (const float4*)(g_h1 + (size_t)s * D1);
    float* ob = g_out1 + (size_t)d * D1 + lane * 8;
    float4 a = hs[lane * 2], b = hs[lane * 2 + 1];
    a.x *= exh; a.y *= exh; a.z *= exh; a.w *= exh;
    b.x *= exh; b.y *= exh; b.z *= exh; b.w *= exh;
    asm volatile("red.global.add.v4.f32 [%0], {%1,%2,%3,%4};"
                 :: "l"(ob), "f"(a.x), "f"(a.y), "f"(a.z), "f"(a.w) : "memory");
    asm volatile("red.global.add.v4.f32 [%0], {%1,%2,%3,%4};"
                 :: "l"(ob + 4), "f"(b.x), "f"(b.y), "f"(b.z), "f"(b.w) : "memory");
}

// finalize layer1: divide by denom, +bias, relu (in-place -> input of GEMM2)
__global__ void finalize1(const float* __restrict__ b1) {
    int i = blockIdx.x * blockDim.x + threadIdx.x;
    if (i >= NN * D1) return;
    int n = i / D1, c = i - n * D1;
    float den = g_den1[n * H1 + (c >> 5)] + 1e-16f;
    float v = g_out1[i] / den + b1[c];
    g_out1[i] = v > 0.f ? v : 0.f;
}

// layer2 edge logits + segment max (thread per edge)
__global__ void edge_logits2(const int* __restrict__ ei) {
    int e = blockIdx.x * blockDim.x + threadIdx.x;
    if (e >= ET) return;
    int s, d;
    if (e < NE) { s = ei[e]; d = ei[NE + e]; } else { s = e - NE; d = s; }
    float v = lrelu(g_as2[s] + g_ad2[d]);
    g_e2[e] = v;
    atomicMax(&g_m2[d], fenc(v));
}

// layer2 edge accumulation: warp per edge; lane covers 2 floats
__global__ void edge_accum2(const int* __restrict__ ei, float* __restrict__ out) {
    int gw   = (blockIdx.x * blockDim.x + threadIdx.x) >> 5;
    int lane = threadIdx.x & 31;
    if (gw >= ET) return;
    int s, d;
    if (gw < NE) { s = ei[gw]; d = ei[NE + gw]; } else { s = gw - NE; d = s; }
    float v  = g_e2[gw];
    float ex = __expf(v - fdec(g_m2[d]));
    if (lane == 0) atomicAdd(&g_den2[d], ex);
    float2 hv = ((const float2*)(g_h2 + (size_t)s * D2))[lane];
    hv.x *= ex; hv.y *= ex;
    asm volatile("red.global.add.v2.f32 [%0], {%1,%2};"
                 :: "l"(out + (size_t)d * D2 + lane * 2), "f"(hv.x), "f"(hv.y)
                 : "memory");
}

__global__ void finalize2(float* __restrict__ out, const float* __restrict__ b2) {
    int i = blockIdx.x * blockDim.x + threadIdx.x;
    if (i >= NN * D2) return;
    float den = g_den2[i >> 6] + 1e-16f;
    out[i] = out[i] / den + b2[i & 63];
}

extern "C" void kernel_launch(void* const* d_in, const int* in_sizes, int n_in,
                              void* d_out, int out_size) {
    const float* x   = (const float*)d_in[0];
    const int*   ei  = (const int*)  d_in[1];
    const float* W1  = (const float*)d_in[2];
    const float* as1 = (const float*)d_in[3];
    const float* ad1 = (const float*)d_in[4];
    const float* b1  = (const float*)d_in[5];
    const float* W2  = (const float*)d_in[6];
    const float* as2 = (const float*)d_in[7];
    const float* ad2 = (const float*)d_in[8];
    const float* b2  = (const float*)d_in[9];
    float* out = (float*)d_out;

    void *p_h1, *p_out1, *p_h2, *p_as1, *p_ad1, *p_as2, *p_ad2;
    cudaGetSymbolAddress(&p_h1,   g_h1);
    cudaGetSymbolAddress(&p_out1, g_out1);
    cudaGetSymbolAddress(&p_h2,   g_h2);
    cudaGetSymbolAddress(&p_as1,  g_as1);
    cudaGetSymbolAddress(&p_ad1,  g_ad1);
    cudaGetSymbolAddress(&p_as2,  g_as2);
    cudaGetSymbolAddress(&p_ad2,  g_ad2);

    // ---- Layer 1 ----
    {
        dim3 grid(D1 / 64, (NN + 63) / 64);
        sgemm<<<grid, 256>>>(x, W1, (float*)p_h1, NN, D1, INC);
    }
    attn_scores<<<(NN * H1 + 255) / 256, 256>>>((const float*)p_h1, as1, ad1,
                                                (float*)p_as1, (float*)p_ad1,
                                                NN * H1, H1, HID);
    init_l1<<<2048, 256>>>();
    edge_logits1<<<(ET * H1 + 255) / 256, 256>>>(ei);
    edge_accum1<<<(ET + 7) / 8, 256>>>(ei);          // warp per edge
    finalize1<<<(NN * D1 + 255) / 256, 256>>>(b1);

    // ---- Layer 2 ----
    {
        dim3 grid(1, (NN + 63) / 64);
        sgemm<<<grid, 256>>>((const float*)p_out1, W2, (float*)p_h2, NN, D2, D1);
    }
    attn_scores<<<(NN + 255) / 256, 256>>>((const float*)p_h2, as2, ad2,
                                           (float*)p_as2, (float*)p_ad2,
                                           NN, 1, D2);
    init_l2<<<1024, 256>>>(out);
    edge_logits2<<<(ET + 255) / 256, 256>>>(ei);
    edge_accum2<<<(ET + 7) / 8, 256>>>(ei, out);     // warp per edge
    finalize2<<<(NN * D2 + 255) / 256, 256>>>(out, b2);
}

// round 2
// speedup vs baseline: 1.1354x; 1.1354x over previous
#include <cuda_runtime.h>

#define NN   50000
#define NE   800000
#define ET   (NE + NN)        // 850000 edges incl self-loops
#define INC  128
#define HID  32
#define H1   8
#define D1   256              // H1*HID
#define D2   64

#define ENC_NEGINF 0x007FFFFFu   // fenc(-inf)

__device__ __forceinline__ unsigned fenc(float f) {
    unsigned u = __float_as_uint(f);
    return (u & 0x80000000u) ? ~u : (u | 0x80000000u);
}
__device__ __forceinline__ float fdec(unsigned u) {
    return __uint_as_float((u & 0x80000000u) ? (u & 0x7FFFFFFFu) : ~u);
}
__device__ __forceinline__ float lrelu(float v) { return v > 0.f ? v : 0.2f * v; }
__device__ __forceinline__ unsigned to_tf32(float f) {
    unsigned r;
    asm("cvt.rna.tf32.f32 %0, %1;" : "=r"(r) : "f"(f));
    return r;
}

// ---- scratch (static device globals; no allocation allowed) ----
__device__ float    g_h1[(size_t)NN * D1];     // x @ W1            [N,256]
__device__ float    g_out1[(size_t)NN * D1];   // layer1 accum / relu'd input to L2
__device__ float    g_as1[NN * H1];
__device__ float    g_ad1[NN * H1];
__device__ unsigned g_m1[NN * H1];
__device__ float    g_den1[NN * H1];

__device__ float    g_h2[(size_t)NN * D2];     // h_relu @ W2       [N,64]
__device__ float    g_as2[NN];
__device__ float    g_ad2[NN];
__device__ unsigned g_m2[NN];
__device__ float    g_den2[NN];

// ============================================================
// TF32 tensor-core GEMM: C[M,N] = A[M,K] * B[K,N], fp32 I/O.
// BM=128, BN=64, BK=32; 256 threads = 8 warps in 4(m) x 2(n);
// warp tile 32x32 = 2 x 4 mma tiles of m16n8k8.
// ============================================================
__device__ __forceinline__ void mma_tf32(float c[4], const unsigned a[4],
                                         const unsigned b[2]) {
    asm volatile(
        "mma.sync.aligned.m16n8k8.row.col.f32.tf32.tf32.f32 "
        "{%0,%1,%2,%3}, {%4,%5,%6,%7}, {%8,%9}, {%0,%1,%2,%3};"
        : "+f"(c[0]), "+f"(c[1]), "+f"(c[2]), "+f"(c[3])
        : "r"(a[0]), "r"(a[1]), "r"(a[2]), "r"(a[3]), "r"(b[0]), "r"(b[1]));
}

__global__ void gemm_tf32(const float* __restrict__ A, const float* __restrict__ B,
                          float* __restrict__ C, int M, int N, int K) {
    const int BM = 128, BN = 64, BK = 32;
    __shared__ unsigned As[BK][BM + 4];   // transposed: As[k][m], tf32 bits
    __shared__ unsigned Bs[BK][BN + 4];   // Bs[k][n], tf32 bits

    int t    = threadIdx.x;
    int warp = t >> 5, lane = t & 31;
    int wm = warp >> 1, wn = warp & 1;    // 4 x 2 warp grid
    int g = lane >> 2, t4 = lane & 3;
    int row0 = blockIdx.y * BM, col0 = blockIdx.x * BN;

    float acc[2][4][4] = {};

    for (int kt = 0; kt < K; kt += BK) {
        // load A tile [BM x BK] -> As[k][m]; 1024 float4 / 256 thr = 4 each
#pragma unroll
        for (int i = 0; i < 4; i++) {
            int idx = t + i * 256;
            int r = idx >> 3, c4 = (idx & 7) * 4;
            int gr = row0 + r;
            float4 v = (gr < M) ? *(const float4*)&A[(size_t)gr * K + kt + c4]
                                : make_float4(0.f, 0.f, 0.f, 0.f);
            As[c4 + 0][r] = to_tf32(v.x);
            As[c4 + 1][r] = to_tf32(v.y);
            As[c4 + 2][r] = to_tf32(v.z);
            As[c4 + 3][r] = to_tf32(v.w);
        }
        // load B tile [BK x BN] -> Bs[k][n]; 512 float4 / 256 thr = 2 each
#pragma unroll
        for (int i = 0; i < 2; i++) {
            int idx = t + i * 256;
            int k = idx >> 4, c4 = (idx & 15) * 4;
            float4 v = *(const float4*)&B[(size_t)(kt + k) * N + col0 + c4];
            Bs[k][c4 + 0] = to_tf32(v.x);
            Bs[k][c4 + 1] = to_tf32(v.y);
            Bs[k][c4 + 2] = to_tf32(v.z);
            Bs[k][c4 + 3] = to_tf32(v.w);
        }
        __syncthreads();

#pragma unroll
        for (int k0 = 0; k0 < BK; k0 += 8) {
            unsigned a[2][4], b[4][2];
#pragma unroll
            for (int mi = 0; mi < 2; mi++) {
                int mb = wm * 32 + mi * 16;
                a[mi][0] = As[k0 + t4][mb + g];
                a[mi][1] = As[k0 + t4][mb + 8 + g];
                a[mi][2] = As[k0 + t4 + 4][mb + g];
                a[mi][3] = As[k0 + t4 + 4][mb + 8 + g];
            }
#pragma unroll
            for (int ni = 0; ni < 4; ni++) {
                int nb = wn * 32 + ni * 8;
                b[ni][0] = Bs[k0 + t4][nb + g];
                b[ni][1] = Bs[k0 + t4 + 4][nb + g];
            }
#pragma unroll
            for (int mi = 0; mi < 2; mi++)
#pragma unroll
                for (int ni = 0; ni < 4; ni++)
                    mma_tf32(acc[mi][ni], a[mi], b[ni]);
        }
        __syncthreads();
    }

    // store
#pragma unroll
    for (int mi = 0; mi < 2; mi++) {
#pragma unroll
        for (int ni = 0; ni < 4; ni++) {
            int col = col0 + wn * 32 + ni * 8 + t4 * 2;
            int r0 = row0 + wm * 32 + mi * 16 + g;
            int r1 = r0 + 8;
            if (r0 < M)
                *(float2*)&C[(size_t)r0 * N + col] =
                    make_float2(acc[mi][ni][0], acc[mi][ni][1]);
            if (r1 < M)
                *(float2*)&C[(size_t)r1 * N + col] =
                    make_float2(acc[mi][ni][2], acc[mi][ni][3]);
        }
    }
}

// per-(node,head) attention dot products
__global__ void attn_scores(const float* __restrict__ h,
                            const float* __restrict__ atts,
                            const float* __restrict__ attd,
                            float* __restrict__ as_, float* __restrict__ ad_,
                            int total, int H, int C) {
    int i = blockIdx.x * blockDim.x + threadIdx.x;
    if (i >= total) return;
    int hh = i % H;
    const float4* hv = (const float4*)(h + (size_t)i * C);
    const float4* sv = (const float4*)(atts + (size_t)hh * C);
    const float4* dv = (const float4*)(attd + (size_t)hh * C);
    float s = 0.f, d = 0.f;
    for (int c = 0; c < C / 4; c++) {
        float4 x = hv[c], a = sv[c], b = dv[c];
        s += x.x * a.x + x.y * a.y + x.z * a.z + x.w * a.w;
        d += x.x * b.x + x.y * b.y + x.z * b.z + x.w * b.w;
    }
    as_[i] = s;
    ad_[i] = d;
}

__global__ void init_l1() {
    size_t i = blockIdx.x * (size_t)blockDim.x + threadIdx.x;
    size_t stride = (size_t)gridDim.x * blockDim.x;
    for (size_t j = i; j < (size_t)NN * D1; j += stride) g_out1[j] = 0.f;
    for (size_t j = i; j < (size_t)NN * H1; j += stride) {
        g_den1[j] = 0.f;
        g_m1[j]   = ENC_NEGINF;
    }
}

__global__ void init_l2(float* __restrict__ out) {
    size_t i = blockIdx.x * (size_t)blockDim.x + threadIdx.x;
    size_t stride = (size_t)gridDim.x * blockDim.x;
    for (size_t j = i; j < (size_t)NN * D2; j += stride) out[j] = 0.f;
    for (size_t j = i; j < (size_t)NN; j += stride) {
        g_den2[j] = 0.f;
        g_m2[j]   = ENC_NEGINF;
    }
}

// layer1 segment max (thread per edge-head); logits recomputed later
__global__ void edge_logits1(const int* __restrict__ ei) {
    int idx = blockIdx.x * blockDim.x + threadIdx.x;
    if (idx >= ET * H1) return;
    int e = idx >> 3, h = idx & 7;
    int s, d;
    if (e < NE) { s = ei[e]; d = ei[NE + e]; } else { s = e - NE; d = s; }
    float v = lrelu(g_as1[s * H1 + h] + g_ad1[d * H1 + h]);
    atomicMax(&g_m1[d * H1 + h], fenc(v));
}

// layer1 edge accumulation: warp per edge; lane c covers 8 floats (head = lane/4)
__global__ void edge_accum1(const int* __restrict__ ei) {
    int gw   = (blockIdx.x * blockDim.x + threadIdx.x) >> 5;
    int lane = threadIdx.x & 31;
    if (gw >= ET) return;
    int s, d;
    if (gw < NE) { s = ei[gw]; d = ei[NE + gw]; } else { s = gw - NE; d = s; }
    float ex = 0.f;
    if (lane < H1) {
        float v = lrelu(g_as1[s * H1 + lane] + g_ad1[d * H1 + lane]);
        float m = fdec(g_m1[d * H1 + lane]);
        ex = __expf(v - m);
        atomicAdd(&g_den1[d * H1 + lane], ex);
    }
    float exh = __shfl_sync(0xffffffffu, ex, lane >> 2);  // head = lane/4
    const float4* hs = (const float4*)(g_h1 + (size_t)s * D1);
    float* ob = g_out1 + (size_t)d * D1 + lane * 8;
    float4 a = hs[lane * 2], b = hs[lane * 2 + 1];
    a.x *= exh; a.y *= exh; a.z *= exh; a.w *= exh;
    b.x *= exh; b.y *= exh; b.z *= exh; b.w *= exh;
    asm volatile("red.global.add.v4.f32 [%0], {%1,%2,%3,%4};"
                 :: "l"(ob), "f"(a.x), "f"(a.y), "f"(a.z), "f"(a.w) : "memory");
    asm volatile("red.global.add.v4.f32 [%0], {%1,%2,%3,%4};"
                 :: "l"(ob + 4), "f"(b.x), "f"(b.y), "f"(b.z), "f"(b.w) : "memory");
}

// finalize layer1: divide by denom, +bias, relu (in-place -> input of GEMM2)
__global__ void finalize1(const float* __restrict__ b1) {
    int i = blockIdx.x * blockDim.x + threadIdx.x;
    if (i >= NN * D1) return;
    int n = i / D1, c = i - n * D1;
    float den = g_den1[n * H1 + (c >> 5)] + 1e-16f;
    float v = g_out1[i] / den + b1[c];
    g_out1[i] = v > 0.f ? v : 0.f;
}

// layer2 segment max (thread per edge)
__global__ void edge_logits2(const int* __restrict__ ei) {
    int e = blockIdx.x * blockDim.x + threadIdx.x;
    if (e >= ET) return;
    int s, d;
    if (e < NE) { s = ei[e]; d = ei[NE + e]; } else { s = e - NE; d = s; }
    float v = lrelu(g_as2[s] + g_ad2[d]);
    atomicMax(&g_m2[d], fenc(v));
}

// layer2 edge accumulation: warp per edge; lane covers 2 floats
__global__ void edge_accum2(const int* __restrict__ ei, float* __restrict__ out) {
    int gw   = (blockIdx.x * blockDim.x + threadIdx.x) >> 5;
    int lane = threadIdx.x & 31;
    if (gw >= ET) return;
    int s, d;
    if (gw < NE) { s = ei[gw]; d = ei[NE + gw]; } else { s = gw - NE; d = s; }
    float v  = lrelu(g_as2[s] + g_ad2[d]);
    float ex = __expf(v - fdec(g_m2[d]));
    if (lane == 0) atomicAdd(&g_den2[d], ex);
    float2 hv = ((const float2*)(g_h2 + (size_t)s * D2))[lane];
    hv.x *= ex; hv.y *= ex;
    asm volatile("red.global.add.v2.f32 [%0], {%1,%2};"
                 :: "l"(out + (size_t)d * D2 + lane * 2), "f"(hv.x), "f"(hv.y)
                 : "memory");
}

__global__ void finalize2(float* __restrict__ out, const float* __restrict__ b2) {
    int i = blockIdx.x * blockDim.x + threadIdx.x;
    if (i >= NN * D2) return;
    float den = g_den2[i >> 6] + 1e-16f;
    out[i] = out[i] / den + b2[i & 63];
}

extern "C" void kernel_launch(void* const* d_in, const int* in_sizes, int n_in,
                              void* d_out, int out_size) {
    const float* x   = (const float*)d_in[0];
    const int*   ei  = (const int*)  d_in[1];
    const float* W1  = (const float*)d_in[2];
    const float* as1 = (const float*)d_in[3];
    const float* ad1 = (const float*)d_in[4];
    const float* b1  = (const float*)d_in[5];
    const float* W2  = (const float*)d_in[6];
    const float* as2 = (const float*)d_in[7];
    const float* ad2 = (const float*)d_in[8];
    const float* b2  = (const float*)d_in[9];
    float* out = (float*)d_out;

    void *p_h1, *p_out1, *p_h2, *p_as1, *p_ad1, *p_as2, *p_ad2;
    cudaGetSymbolAddress(&p_h1,   g_h1);
    cudaGetSymbolAddress(&p_out1, g_out1);
    cudaGetSymbolAddress(&p_h2,   g_h2);
    cudaGetSymbolAddress(&p_as1,  g_as1);
    cudaGetSymbolAddress(&p_ad1,  g_ad1);
    cudaGetSymbolAddress(&p_as2,  g_as2);
    cudaGetSymbolAddress(&p_ad2,  g_ad2);

    // ---- Layer 1 ----
    {
        dim3 grid(D1 / 64, (NN + 127) / 128);
        gemm_tf32<<<grid, 256>>>(x, W1, (float*)p_h1, NN, D1, INC);
    }
    attn_scores<<<(NN * H1 + 255) / 256, 256>>>((const float*)p_h1, as1, ad1,
                                                (float*)p_as1, (float*)p_ad1,
                                                NN * H1, H1, HID);
    init_l1<<<2048, 256>>>();
    edge_logits1<<<(ET * H1 + 255) / 256, 256>>>(ei);
    edge_accum1<<<(ET + 7) / 8, 256>>>(ei);          // warp per edge
    finalize1<<<(NN * D1 + 255) / 256, 256>>>(b1);

    // ---- Layer 2 ----
    {
        dim3 grid(1, (NN + 127) / 128);
        gemm_tf32<<<grid, 256>>>((const float*)p_out1, W2, (float*)p_h2, NN, D2, D1);
    }
    attn_scores<<<(NN + 255) / 256, 256>>>((const float*)p_h2, as2, ad2,
                                           (float*)p_as2, (float*)p_ad2,
                                           NN, 1, D2);
    init_l2<<<1024, 256>>>(out);
    edge_logits2<<<(ET + 255) / 256, 256>>>(ei);
    edge_accum2<<<(ET + 7) / 8, 256>>>(ei, out);     // warp per edge
    finalize2<<<(NN * D2 + 255) / 256, 256>>>(out, b2);
}

// round 3
// speedup vs baseline: 2.2088x; 1.9454x over previous
#include <cuda_runtime.h>

#define NN   50000
#define NE   800000
#define ET   (NE + NN)        // 850000 edges incl self-loops
#define INC  128
#define HID  32
#define H1   8
#define D1   256              // H1*HID
#define D2   64

#define SCAN_BLK 1024
#define NCHUNK   ((NN + SCAN_BLK - 1) / SCAN_BLK)   // 49

__device__ __forceinline__ float lrelu(float v) { return v > 0.f ? v : 0.2f * v; }
__device__ __forceinline__ unsigned to_tf32(float f) {
    unsigned r;
    asm("cvt.rna.tf32.f32 %0, %1;" : "=r"(r) : "f"(f));
    return r;
}

// ---- scratch (static device globals) ----
__device__ float    g_h1[(size_t)NN * D1];     // x @ W1
__device__ float    g_out1[(size_t)NN * D1];   // layer1 output (relu'd)
__device__ float    g_as1[NN * H1];
__device__ float    g_ad1[NN * H1];
__device__ float    g_m1[NN * H1];
__device__ float    g_den1[NN * H1];

__device__ float    g_h2[(size_t)NN * D2];
__device__ float    g_as2[NN];
__device__ float    g_ad2[NN];
__device__ float    g_m2[NN];
__device__ float    g_den2[NN];

// CSR (dst-sorted), rebuilt every launch
__device__ int g_cnt[NN];
__device__ int g_tmp[NN];          // per-chunk exclusive scan
__device__ int g_part[NCHUNK];
__device__ int g_psc[NCHUNK];
__device__ int g_row[NN + 1];
__device__ int g_cur[NN];
__device__ int g_csr_src[ET];

// ============================================================
// CSR build
// ============================================================
__global__ void cnt_init() {
    int i = blockIdx.x * blockDim.x + threadIdx.x;
    if (i < NN) g_cnt[i] = 1;      // self-loop
}
__global__ void hist(const int* __restrict__ ei) {
    int e = blockIdx.x * blockDim.x + threadIdx.x;
    if (e < NE) atomicAdd(&g_cnt[ei[NE + e]], 1);
}
__global__ void scanA() {
    __shared__ int sh[SCAN_BLK];
    int t = threadIdx.x, i = blockIdx.x * SCAN_BLK + t;
    int v = (i < NN) ? g_cnt[i] : 0;
    sh[t] = v;
    __syncthreads();
#pragma unroll
    for (int off = 1; off < SCAN_BLK; off <<= 1) {
        int x = (t >= off) ? sh[t - off] : 0;
        __syncthreads();
        sh[t] += x;
        __syncthreads();
    }
    if (i < NN) g_tmp[i] = sh[t] - v;           // exclusive
    if (t == SCAN_BLK - 1) g_part[blockIdx.x] = sh[t];
}
__global__ void scanB() {
    __shared__ int sh[64];
    int t = threadIdx.x;
    int v = (t < NCHUNK) ? g_part[t] : 0;
    sh[t] = v;
    __syncthreads();
#pragma unroll
    for (int off = 1; off < 64; off <<= 1) {
        int x = (t >= off) ? sh[t - off] : 0;
        __syncthreads();
        sh[t] += x;
        __syncthreads();
    }
    if (t < NCHUNK) g_psc[t] = sh[t] - v;       // exclusive
}
__global__ void scanC() {
    int i = blockIdx.x * SCAN_BLK + threadIdx.x;
    if (i < NN) {
        int r = g_tmp[i] + g_psc[blockIdx.x];
        g_row[i] = r;
        g_cur[i] = r;
    }
    if (i == 0) g_row[NN] = ET;
}
__global__ void scatter(const int* __restrict__ ei) {
    int e = blockIdx.x * blockDim.x + threadIdx.x;
    if (e >= ET) return;
    int s, d;
    if (e < NE) { s = ei[e]; d = ei[NE + e]; } else { s = e - NE; d = s; }
    int pos = atomicAdd(&g_cur[d], 1);
    g_csr_src[pos] = s;
}

// ============================================================
// TF32 tensor-core GEMM (as round 2)
// ============================================================
__device__ __forceinline__ void mma_tf32(float c[4], const unsigned a[4],
                                         const unsigned b[2]) {
    asm volatile(
        "mma.sync.aligned.m16n8k8.row.col.f32.tf32.tf32.f32 "
        "{%0,%1,%2,%3}, {%4,%5,%6,%7}, {%8,%9}, {%0,%1,%2,%3};"
        : "+f"(c[0]), "+f"(c[1]), "+f"(c[2]), "+f"(c[3])
        : "r"(a[0]), "r"(a[1]), "r"(a[2]), "r"(a[3]), "r"(b[0]), "r"(b[1]));
}

__global__ void gemm_tf32(const float* __restrict__ A, const float* __restrict__ B,
                          float* __restrict__ C, int M, int N, int K) {
    const int BM = 128, BN = 64, BK = 32;
    __shared__ unsigned As[BK][BM + 4];
    __shared__ unsigned Bs[BK][BN + 4];

    int t    = threadIdx.x;
    int warp = t >> 5, lane = t & 31;
    int wm = warp >> 1, wn = warp & 1;
    int g = lane >> 2, t4 = lane & 3;
    int row0 = blockIdx.y * BM, col0 = blockIdx.x * BN;

    float acc[2][4][4] = {};

    for (int kt = 0; kt < K; kt += BK) {
#pragma unroll
        for (int i = 0; i < 4; i++) {
            int idx = t + i * 256;
            int r = idx >> 3, c4 = (idx & 7) * 4;
            int gr = row0 + r;
            float4 v = (gr < M) ? *(const float4*)&A[(size_t)gr * K + kt + c4]
                                : make_float4(0.f, 0.f, 0.f, 0.f);
            As[c4 + 0][r] = to_tf32(v.x);
            As[c4 + 1][r] = to_tf32(v.y);
            As[c4 + 2][r] = to_tf32(v.z);
            As[c4 + 3][r] = to_tf32(v.w);
        }
#pragma unroll
        for (int i = 0; i < 2; i++) {
            int idx = t + i * 256;
            int k = idx >> 4, c4 = (idx & 15) * 4;
            float4 v = *(const float4*)&B[(size_t)(kt + k) * N + col0 + c4];
            Bs[k][c4 + 0] = to_tf32(v.x);
            Bs[k][c4 + 1] = to_tf32(v.y);
            Bs[k][c4 + 2] = to_tf32(v.z);
            Bs[k][c4 + 3] = to_tf32(v.w);
        }
        __syncthreads();

#pragma unroll
        for (int k0 = 0; k0 < BK; k0 += 8) {
            unsigned a[2][4], b[4][2];
#pragma unroll
            for (int mi = 0; mi < 2; mi++) {
                int mb = wm * 32 + mi * 16;
                a[mi][0] = As[k0 + t4][mb + g];
                a[mi][1] = As[k0 + t4][mb + 8 + g];
                a[mi][2] = As[k0 + t4 + 4][mb + g];
                a[mi][3] = As[k0 + t4 + 4][mb + 8 + g];
            }
#pragma unroll
            for (int ni = 0; ni < 4; ni++) {
                int nb = wn * 32 + ni * 8;
                b[ni][0] = Bs[k0 + t4][nb + g];
                b[ni][1] = Bs[k0 + t4 + 4][nb + g];
            }
#pragma unroll
            for (int mi = 0; mi < 2; mi++)
#pragma unroll
                for (int ni = 0; ni < 4; ni++)
                    mma_tf32(acc[mi][ni], a[mi], b[ni]);
        }
        __syncthreads();
    }

#pragma unroll
    for (int mi = 0; mi < 2; mi++) {
#pragma unroll
        for (int ni = 0; ni < 4; ni++) {
            int col = col0 + wn * 32 + ni * 8 + t4 * 2;
            int r0 = row0 + wm * 32 + mi * 16 + g;
            int r1 = r0 + 8;
            if (r0 < M)
                *(float2*)&C[(size_t)r0 * N + col] =
                    make_float2(acc[mi][ni][0], acc[mi][ni][1]);
            if (r1 < M)
                *(float2*)&C[(size_t)r1 * N + col] =
                    make_float2(acc[mi][ni][2], acc[mi][ni][3]);
        }
    }
}

// per-(node,head) attention dot products
__global__ void attn_scores(const float* __restrict__ h,
                            const float* __restrict__ atts,
                            const float* __restrict__ attd,
                            float* __restrict__ as_, float* __restrict__ ad_,
                            int total, int H, int C) {
    int i = blockIdx.x * blockDim.x + threadIdx.x;
    if (i >= total) return;
    int hh = i % H;
    const float4* hv = (const float4*)(h + (size_t)i * C);
    const float4* sv = (const float4*)(atts + (size_t)hh * C);
    const float4* dv = (const float4*)(attd + (size_t)hh * C);
    float s = 0.f, d = 0.f;
    for (int c = 0; c < C / 4; c++) {
        float4 x = hv[c], a = sv[c], b = dv[c];
        s += x.x * a.x + x.y * a.y + x.z * a.z + x.w * a.w;
        d += x.x * b.x + x.y * b.y + x.z * b.z + x.w * b.w;
    }
    as_[i] = s;
    ad_[i] = d;
}

// ---- layer1 online softmax: thread per (node,head) ----
__global__ void soft1() {
    int i = blockIdx.x * blockDim.x + threadIdx.x;
    if (i >= NN * H1) return;
    int n = i >> 3, h = i & 7;
    float adh = g_ad1[i];
    int beg = g_row[n], end = g_row[n + 1];
    float m = -3.4e38f, ssum = 0.f;
    for (int j = beg; j < end; j++) {
        int s = g_csr_src[j];
        float v = lrelu(g_as1[s * H1 + h] + adh);
        if (v > m) {
            ssum = ssum * __expf(m - v) + 1.f;
            m = v;
        } else {
            ssum += __expf(v - m);
        }
    }
    g_m1[i]   = m;
    g_den1[i] = ssum;
}

// ---- layer1 aggregation: warp per dst node, fused divide+bias+relu ----
__global__ void aggr1(const float* __restrict__ b1) {
    int w    = (blockIdx.x * blockDim.x + threadIdx.x) >> 5;
    int lane = threadIdx.x & 31;
    if (w >= NN) return;
    int h8   = lane & 7;        // head used for ex computation
    int head = lane >> 2;       // head owning this lane's 8 features

    float adh = g_ad1[w * H1 + h8];
    float mh  = g_m1[w * H1 + h8];
    int beg = g_row[w], end = g_row[w + 1];

    float4 accA = {0.f, 0.f, 0.f, 0.f}, accB = {0.f, 0.f, 0.f, 0.f};
    for (int j = beg; j < end; j++) {
        int s = g_csr_src[j];
        float v  = lrelu(g_as1[s * H1 + h8] + adh);
        float ex = __expf(v - mh);
        float exh = __shfl_sync(0xffffffffu, ex, head);
        const float4* hs = (const float4*)(g_h1 + (size_t)s * D1);
        float4 a = hs[lane * 2], b = hs[lane * 2 + 1];
        accA.x += exh * a.x; accA.y += exh * a.y;
        accA.z += exh * a.z; accA.w += exh * a.w;
        accB.x += exh * b.x; accB.y += exh * b.y;
        accB.z += exh * b.z; accB.w += exh * b.w;
    }
    float inv = 1.f / (g_den1[w * H1 + head] + 1e-16f);
    const float4* bb = (const float4*)(b1 + lane * 8);
    float4 b0 = bb[0], b1v = bb[1];
    float4 oA, oB;
    oA.x = fmaxf(accA.x * inv + b0.x, 0.f);
    oA.y = fmaxf(accA.y * inv + b0.y, 0.f);
    oA.z = fmaxf(accA.z * inv + b0.z, 0.f);
    oA.w = fmaxf(accA.w * inv + b0.w, 0.f);
    oB.x = fmaxf(accB.x * inv + b1v.x, 0.f);
    oB.y = fmaxf(accB.y * inv + b1v.y, 0.f);
    oB.z = fmaxf(accB.z * inv + b1v.z, 0.f);
    oB.w = fmaxf(accB.w * inv + b1v.w, 0.f);
    float4* ob = (float4*)(g_out1 + (size_t)w * D1 + lane * 8);
    ob[0] = oA;
    ob[1] = oB;
}

// ---- layer2 online softmax: thread per node ----
__global__ void soft2() {
    int n = blockIdx.x * blockDim.x + threadIdx.x;
    if (n >= NN) return;
    float adh = g_ad2[n];
    int beg = g_row[n], end = g_row[n + 1];
    float m = -3.4e38f, ssum = 0.f;
    for (int j = beg; j < end; j++) {
        int s = g_csr_src[j];
        float v = lrelu(g_as2[s] + adh);
        if (v > m) {
            ssum = ssum * __expf(m - v) + 1.f;
            m = v;
        } else {
            ssum += __expf(v - m);
        }
    }
    g_m2[n]   = m;
    g_den2[n] = ssum;
}

// ---- layer2 aggregation: warp per dst node ----
__global__ void aggr2(float* __restrict__ out, const float* __restrict__ b2) {
    int w    = (blockIdx.x * blockDim.x + threadIdx.x) >> 5;
    int lane = threadIdx.x & 31;
    if (w >= NN) return;
    float adh = g_ad2[w];
    float mh  = g_m2[w];
    int beg = g_row[w], end = g_row[w + 1];

    float2 acc = {0.f, 0.f};
    for (int j = beg; j < end; j++) {
        int s = g_csr_src[j];
        float v  = lrelu(g_as2[s] + adh);
        float ex = __expf(v - mh);
        float2 hv = ((const float2*)(g_h2 + (size_t)s * D2))[lane];
        acc.x += ex * hv.x;
        acc.y += ex * hv.y;
    }
    float inv = 1.f / (g_den2[w] + 1e-16f);
    float2 bv = ((const float2*)b2)[lane];
    float2 o  = {acc.x * inv + bv.x, acc.y * inv + bv.y};
    ((float2*)(out + (size_t)w * D2))[lane] = o;
}

extern "C" void kernel_launch(void* const* d_in, const int* in_sizes, int n_in,
                              void* d_out, int out_size) {
    const float* x   = (const float*)d_in[0];
    const int*   ei  = (const int*)  d_in[1];
    const float* W1  = (const float*)d_in[2];
    const float* as1 = (const float*)d_in[3];
    const float* ad1 = (const float*)d_in[4];
    const float* b1  = (const float*)d_in[5];
    const float* W2  = (const float*)d_in[6];
    const float* as2 = (const float*)d_in[7];
    const float* ad2 = (const float*)d_in[8];
    const float* b2  = (const float*)d_in[9];
    float* out = (float*)d_out;

    void *p_h1, *p_out1, *p_h2, *p_as1, *p_ad1, *p_as2, *p_ad2;
    cudaGetSymbolAddress(&p_h1,   g_h1);
    cudaGetSymbolAddress(&p_out1, g_out1);
    cudaGetSymbolAddress(&p_h2,   g_h2);
    cudaGetSymbolAddress(&p_as1,  g_as1);
    cudaGetSymbolAddress(&p_ad1,  g_ad1);
    cudaGetSymbolAddress(&p_as2,  g_as2);
    cudaGetSymbolAddress(&p_ad2,  g_ad2);

    // ---- CSR build (shared by both layers) ----
    cnt_init<<<(NN + 255) / 256, 256>>>();
    hist<<<(NE + 255) / 256, 256>>>(ei);
    scanA<<<NCHUNK, SCAN_BLK>>>();
    scanB<<<1, 64>>>();
    scanC<<<NCHUNK, SCAN_BLK>>>();
    scatter<<<(ET + 255) / 256, 256>>>(ei);

    // ---- Layer 1 ----
    {
        dim3 grid(D1 / 64, (NN + 127) / 128);
        gemm_tf32<<<grid, 256>>>(x, W1, (float*)p_h1, NN, D1, INC);
    }
    attn_scores<<<(NN * H1 + 255) / 256, 256>>>((const float*)p_h1, as1, ad1,
                                                (float*)p_as1, (float*)p_ad1,
                                                NN * H1, H1, HID);
    soft1<<<(NN * H1 + 255) / 256, 256>>>();
    aggr1<<<(NN + 7) / 8, 256>>>(b1);

    // ---- Layer 2 ----
    {
        dim3 grid(1, (NN + 127) / 128);
        gemm_tf32<<<grid, 256>>>((const float*)p_out1, W2, (float*)p_h2, NN, D2, D1);
    }
    attn_scores<<<(NN + 255) / 256, 256>>>((const float*)p_h2, as2, ad2,
                                           (float*)p_as2, (float*)p_ad2,
                                           NN, 1, D2);
    soft2<<<(NN + 255) / 256, 256>>>();
    aggr2<<<(NN + 7) / 8, 256>>>(out, b2);
}

// round 4
// speedup vs baseline: 2.5544x; 1.1565x over previous
#include <cuda_runtime.h>
#include <cuda_fp16.h>

#define NN   50000
#define NE   800000
#define ET   (NE + NN)        // 850000 edges incl self-loops
#define INC  128
#define HID  32
#define H1   8
#define D1   256              // H1*HID
#define D2   64

#define SCAN_BLK 1024
#define NCHUNK   ((NN + SCAN_BLK - 1) / SCAN_BLK)   // 49

__device__ __forceinline__ float lrelu(float v) { return v > 0.f ? v : 0.2f * v; }
__device__ __forceinline__ unsigned to_tf32(float f) {
    unsigned r;
    asm("cvt.rna.tf32.f32 %0, %1;" : "=r"(r) : "f"(f));
    return r;
}

// ---- scratch (static device globals) ----
__device__ __half   g_h1[(size_t)NN * D1];     // x @ W1, fp16
__device__ float    g_out1[(size_t)NN * D1];   // layer1 output (relu'd), fp32
__device__ float    g_as1[NN * H1];
__device__ float    g_ad1[NN * H1];

__device__ __half   g_h2[(size_t)NN * D2];     // fp16
__device__ float    g_as2[NN];
__device__ float    g_ad2[NN];

// CSR (dst-sorted), rebuilt every launch
__device__ int g_cnt[NN];
__device__ int g_tmp[NN];
__device__ int g_part[NCHUNK];
__device__ int g_psc[NCHUNK];
__device__ int g_row[NN + 1];
__device__ int g_cur[NN];
__device__ int g_csr_src[ET];

// ============================================================
// CSR build
// ============================================================
__global__ void cnt_init() {
    int i = blockIdx.x * blockDim.x + threadIdx.x;
    if (i < NN) g_cnt[i] = 1;      // self-loop
}
__global__ void hist(const int* __restrict__ ei) {
    int e = blockIdx.x * blockDim.x + threadIdx.x;
    if (e < NE) atomicAdd(&g_cnt[ei[NE + e]], 1);
}
__global__ void scanA() {
    __shared__ int sh[SCAN_BLK];
    int t = threadIdx.x, i = blockIdx.x * SCAN_BLK + t;
    int v = (i < NN) ? g_cnt[i] : 0;
    sh[t] = v;
    __syncthreads();
#pragma unroll
    for (int off = 1; off < SCAN_BLK; off <<= 1) {
        int x = (t >= off) ? sh[t - off] : 0;
        __syncthreads();
        sh[t] += x;
        __syncthreads();
    }
    if (i < NN) g_tmp[i] = sh[t] - v;
    if (t == SCAN_BLK - 1) g_part[blockIdx.x] = sh[t];
}
__global__ void scanB() {
    __shared__ int sh[64];
    int t = threadIdx.x;
    int v = (t < NCHUNK) ? g_part[t] : 0;
    sh[t] = v;
    __syncthreads();
#pragma unroll
    for (int off = 1; off < 64; off <<= 1) {
        int x = (t >= off) ? sh[t - off] : 0;
        __syncthreads();
        sh[t] += x;
        __syncthreads();
    }
    if (t < NCHUNK) g_psc[t] = sh[t] - v;
}
__global__ void scanC() {
    int i = blockIdx.x * SCAN_BLK + threadIdx.x;
    if (i < NN) {
        int r = g_tmp[i] + g_psc[blockIdx.x];
        g_row[i] = r;
        g_cur[i] = r;
    }
    if (i == 0) g_row[NN] = ET;
}
__global__ void scatter(const int* __restrict__ ei) {
    int e = blockIdx.x * blockDim.x + threadIdx.x;
    if (e >= ET) return;
    int s, d;
    if (e < NE) { s = ei[e]; d = ei[NE + e]; } else { s = e - NE; d = s; }
    int pos = atomicAdd(&g_cur[d], 1);
    g_csr_src[pos] = s;
}

// ============================================================
// TF32 tensor-core GEMM, fp16 output
// BM=128, BN=64, BK=32; 256 thr; warp tile 32x32
// ============================================================
__device__ __forceinline__ void mma_tf32(float c[4], const unsigned a[4],
                                         const unsigned b[2]) {
    asm volatile(
        "mma.sync.aligned.m16n8k8.row.col.f32.tf32.tf32.f32 "
        "{%0,%1,%2,%3}, {%4,%5,%6,%7}, {%8,%9}, {%0,%1,%2,%3};"
        : "+f"(c[0]), "+f"(c[1]), "+f"(c[2]), "+f"(c[3])
        : "r"(a[0]), "r"(a[1]), "r"(a[2]), "r"(a[3]), "r"(b[0]), "r"(b[1]));
}

__global__ void gemm_tf32_h(const float* __restrict__ A, const float* __restrict__ B,
                            __half* __restrict__ C, int M, int N, int K) {
    const int BM = 128, BN = 64, BK = 32;
    __shared__ unsigned As[BK][BM + 4];
    __shared__ unsigned Bs[BK][BN + 4];

    int t    = threadIdx.x;
    int warp = t >> 5, lane = t & 31;
    int wm = warp >> 1, wn = warp & 1;
    int g = lane >> 2, t4 = lane & 3;
    int row0 = blockIdx.y * BM, col0 = blockIdx.x * BN;

    float acc[2][4][4] = {};

    for (int kt = 0; kt < K; kt += BK) {
#pragma unroll
        for (int i = 0; i < 4; i++) {
            int idx = t + i * 256;
            int r = idx >> 3, c4 = (idx & 7) * 4;
            int gr = row0 + r;
            float4 v = (gr < M) ? *(const float4*)&A[(size_t)gr * K + kt + c4]
                                : make_float4(0.f, 0.f, 0.f, 0.f);
            As[c4 + 0][r] = to_tf32(v.x);
            As[c4 + 1][r] = to_tf32(v.y);
            As[c4 + 2][r] = to_tf32(v.z);
            As[c4 + 3][r] = to_tf32(v.w);
        }
#pragma unroll
        for (int i = 0; i < 2; i++) {
            int idx = t + i * 256;
            int k = idx >> 4, c4 = (idx & 15) * 4;
            float4 v = *(const float4*)&B[(size_t)(kt + k) * N + col0 + c4];
            Bs[k][c4 + 0] = to_tf32(v.x);
            Bs[k][c4 + 1] = to_tf32(v.y);
            Bs[k][c4 + 2] = to_tf32(v.z);
            Bs[k][c4 + 3] = to_tf32(v.w);
        }
        __syncthreads();

#pragma unroll
        for (int k0 = 0; k0 < BK; k0 += 8) {
            unsigned a[2][4], b[4][2];
#pragma unroll
            for (int mi = 0; mi < 2; mi++) {
                int mb = wm * 32 + mi * 16;
                a[mi][0] = As[k0 + t4][mb + g];
                a[mi][1] = As[k0 + t4][mb + 8 + g];
                a[mi][2] = As[k0 + t4 + 4][mb + g];
                a[mi][3] = As[k0 + t4 + 4][mb + 8 + g];
            }
#pragma unroll
            for (int ni = 0; ni < 4; ni++) {
                int nb = wn * 32 + ni * 8;
                b[ni][0] = Bs[k0 + t4][nb + g];
                b[ni][1] = Bs[k0 + t4 + 4][nb + g];
            }
#pragma unroll
            for (int mi = 0; mi < 2; mi++)
#pragma unroll
                for (int ni = 0; ni < 4; ni++)
                    mma_tf32(acc[mi][ni], a[mi], b[ni]);
        }
        __syncthreads();
    }

#pragma unroll
    for (int mi = 0; mi < 2; mi++) {
#pragma unroll
        for (int ni = 0; ni < 4; ni++) {
            int col = col0 + wn * 32 + ni * 8 + t4 * 2;
            int r0 = row0 + wm * 32 + mi * 16 + g;
            int r1 = r0 + 8;
            if (r0 < M)
                *(__half2*)&C[(size_t)r0 * N + col] =
                    __floats2half2_rn(acc[mi][ni][0], acc[mi][ni][1]);
            if (r1 < M)
                *(__half2*)&C[(size_t)r1 * N + col] =
                    __floats2half2_rn(acc[mi][ni][2], acc[mi][ni][3]);
        }
    }
}

// per-(node,head) attention dot products (fp16 h)
__global__ void attn_scores_h(const __half* __restrict__ h,
                              const float* __restrict__ atts,
                              const float* __restrict__ attd,
                              float* __restrict__ as_, float* __restrict__ ad_,
                              int total, int H, int C) {
    int i = blockIdx.x * blockDim.x + threadIdx.x;
    if (i >= total) return;
    int hh = i % H;
    const __half2* hv = (const __half2*)(h + (size_t)i * C);
    const float2*  sv = (const float2*)(atts + (size_t)hh * C);
    const float2*  dv = (const float2*)(attd + (size_t)hh * C);
    float s = 0.f, d = 0.f;
    for (int c = 0; c < C / 2; c++) {
        float2 x = __half22float2(hv[c]);
        float2 a = sv[c], b = dv[c];
        s += x.x * a.x + x.y * a.y;
        d += x.x * b.x + x.y * b.y;
    }
    as_[i] = s;
    ad_[i] = d;
}

// ---- layer1: single-pass softmax+aggregation (no max subtraction) ----
// warp per dst node; lanes 0-7 own per-head exp/den; each lane owns 8 features.
__global__ void aggr1(const float* __restrict__ b1) {
    int w    = (blockIdx.x * blockDim.x + threadIdx.x) >> 5;
    int lane = threadIdx.x & 31;
    if (w >= NN) return;
    int h8   = lane & 7;
    int head = lane >> 2;

    float adh = g_ad1[w * H1 + h8];
    int beg = g_row[w], end = g_row[w + 1];

    float den = 0.f;
    float acc[8] = {};
    for (int j = beg; j < end; j++) {
        int s = g_csr_src[j];
        float v  = lrelu(g_as1[s * H1 + h8] + adh);
        float ex = __expf(v);
        den += ex;                                    // valid in lanes 0-7
        float exh = __shfl_sync(0xffffffffu, ex, head);
        float4 raw = *(const float4*)(g_h1 + (size_t)s * D1 + lane * 8);
        const __half2* hp = (const __half2*)&raw;
#pragma unroll
        for (int q = 0; q < 4; q++) {
            float2 f = __half22float2(hp[q]);
            acc[q * 2 + 0] += exh * f.x;
            acc[q * 2 + 1] += exh * f.y;
        }
    }
    float denh = __shfl_sync(0xffffffffu, den, head);
    float inv  = 1.f / (denh + 1e-16f);
    const float* bb = b1 + lane * 8;
    float4 o0, o1;
    o0.x = fmaxf(acc[0] * inv + bb[0], 0.f);
    o0.y = fmaxf(acc[1] * inv + bb[1], 0.f);
    o0.z = fmaxf(acc[2] * inv + bb[2], 0.f);
    o0.w = fmaxf(acc[3] * inv + bb[3], 0.f);
    o1.x = fmaxf(acc[4] * inv + bb[4], 0.f);
    o1.y = fmaxf(acc[5] * inv + bb[5], 0.f);
    o1.z = fmaxf(acc[6] * inv + bb[6], 0.f);
    o1.w = fmaxf(acc[7] * inv + bb[7], 0.f);
    float4* ob = (float4*)(g_out1 + (size_t)w * D1 + lane * 8);
    ob[0] = o0;
    ob[1] = o1;
}

// ---- layer2: single-pass; warp per dst node, 2 features per lane ----
__global__ void aggr2(float* __restrict__ out, const float* __restrict__ b2) {
    int w    = (blockIdx.x * blockDim.x + threadIdx.x) >> 5;
    int lane = threadIdx.x & 31;
    if (w >= NN) return;
    float adh = g_ad2[w];
    int beg = g_row[w], end = g_row[w + 1];

    float den = 0.f;
    float2 acc = {0.f, 0.f};
    for (int j = beg; j < end; j++) {
        int s = g_csr_src[j];
        float v  = lrelu(g_as2[s] + adh);
        float ex = __expf(v);
        den += ex;
        float2 hv = __half22float2(((const __half2*)(g_h2 + (size_t)s * D2))[lane]);
        acc.x += ex * hv.x;
        acc.y += ex * hv.y;
    }
    float inv = 1.f / (den + 1e-16f);
    float2 bv = ((const float2*)b2)[lane];
    float2 o  = {acc.x * inv + bv.x, acc.y * inv + bv.y};
    ((float2*)(out + (size_t)w * D2))[lane] = o;
}

extern "C" void kernel_launch(void* const* d_in, const int* in_sizes, int n_in,
                              void* d_out, int out_size) {
    const float* x   = (const float*)d_in[0];
    const int*   ei  = (const int*)  d_in[1];
    const float* W1  = (const float*)d_in[2];
    const float* as1 = (const float*)d_in[3];
    const float* ad1 = (const float*)d_in[4];
    const float* b1  = (const float*)d_in[5];
    const float* W2  = (const float*)d_in[6];
    const float* as2 = (const float*)d_in[7];
    const float* ad2 = (const float*)d_in[8];
    const float* b2  = (const float*)d_in[9];
    float* out = (float*)d_out;

    void *p_h1, *p_out1, *p_h2, *p_as1, *p_ad1, *p_as2, *p_ad2;
    cudaGetSymbolAddress(&p_h1,   g_h1);
    cudaGetSymbolAddress(&p_out1, g_out1);
    cudaGetSymbolAddress(&p_h2,   g_h2);
    cudaGetSymbolAddress(&p_as1,  g_as1);
    cudaGetSymbolAddress(&p_ad1,  g_ad1);
    cudaGetSymbolAddress(&p_as2,  g_as2);
    cudaGetSymbolAddress(&p_ad2,  g_ad2);

    // ---- CSR build (shared by both layers) ----
    cnt_init<<<(NN + 255) / 256, 256>>>();
    hist<<<(NE + 255) / 256, 256>>>(ei);
    scanA<<<NCHUNK, SCAN_BLK>>>();
    scanB<<<1, 64>>>();
    scanC<<<NCHUNK, SCAN_BLK>>>();
    scatter<<<(ET + 255) / 256, 256>>>(ei);

    // ---- Layer 1 ----
    {
        dim3 grid(D1 / 64, (NN + 127) / 128);
        gemm_tf32_h<<<grid, 256>>>(x, W1, (__half*)p_h1, NN, D1, INC);
    }
    attn_scores_h<<<(NN * H1 + 255) / 256, 256>>>((const __half*)p_h1, as1, ad1,
                                                  (float*)p_as1, (float*)p_ad1,
                                                  NN * H1, H1, HID);
    aggr1<<<(NN + 7) / 8, 256>>>(b1);

    // ---- Layer 2 ----
    {
        dim3 grid(1, (NN + 127) / 128);
        gemm_tf32_h<<<grid, 256>>>((const float*)p_out1, W2, (__half*)p_h2, NN, D2, D1);
    }
    attn_scores_h<<<(NN + 255) / 256, 256>>>((const __half*)p_h2, as2, ad2,
                                             (float*)p_as2, (float*)p_ad2,
                                             NN, 1, D2);
    aggr2<<<(NN + 7) / 8, 256>>>(out, b2);
}

// round 5
// speedup vs baseline: 2.9677x; 1.1618x over previous
#include <cuda_runtime.h>
#include <cuda_fp16.h>

#define NN   50000
#define NE   800000
#define ET   (NE + NN)
#define INC  128
#define HID  32
#define H1   8
#define D1   256
#define D2   64

#define SCAN_BLK 1024
#define NCHUNK   ((NN + SCAN_BLK - 1) / SCAN_BLK)   // 49

__device__ __forceinline__ float lrelu(float v) { return v > 0.f ? v : 0.2f * v; }
__device__ __forceinline__ unsigned to_tf32(float f) {
    unsigned r;
    asm("cvt.rna.tf32.f32 %0, %1;" : "=r"(r) : "f"(f));
    return r;
}

// ---- scratch ----
__device__ __half   g_h1[(size_t)NN * D1];
__device__ __half   g_out1[(size_t)NN * D1];   // layer1 output (relu'd), fp16
__device__ float    g_as1[NN * H1];
__device__ float    g_ad1[NN * H1];
__device__ __half   g_h2[(size_t)NN * D2];
__device__ float    g_as2[NN];
__device__ float    g_ad2[NN];

// CSR
__device__ int g_cnt[NN];
__device__ int g_row[NN + 1];
__device__ int g_cur[NN];
__device__ int g_csr_src[ET];

// ============================================================
// CSR build
// ============================================================
__global__ void cnt_init() {
    int i = blockIdx.x * blockDim.x + threadIdx.x;
    if (i < NN) g_cnt[i] = 1;      // self-loop
}
__global__ void hist(const int* __restrict__ ei) {
    int e = blockIdx.x * blockDim.x + threadIdx.x;
    if (e < NE) atomicAdd(&g_cnt[ei[NE + e]], 1);
}
// single-block scan over all NN counts (49 chunks of 1024)
__global__ void scan_fused() {
    __shared__ int wsum[32];
    __shared__ int s_carry;
    int t = threadIdx.x, lane = t & 31, wid = t >> 5;
    if (t == 0) s_carry = 0;
    __syncthreads();
    for (int chunk = 0; chunk < NCHUNK; chunk++) {
        int i = chunk * SCAN_BLK + t;
        int v = (i < NN) ? g_cnt[i] : 0;
        int x = v;
#pragma unroll
        for (int o = 1; o < 32; o <<= 1) {
            int y = __shfl_up_sync(0xffffffffu, x, o);
            if (lane >= o) x += y;
        }
        if (lane == 31) wsum[wid] = x;
        __syncthreads();
        if (wid == 0) {
            int w = wsum[lane];
#pragma unroll
            for (int o = 1; o < 32; o <<= 1) {
                int y = __shfl_up_sync(0xffffffffu, w, o);
                if (lane >= o) w += y;
            }
            wsum[lane] = w;
        }
        __syncthreads();
        int base = s_carry + (wid ? wsum[wid - 1] : 0);
        int excl = base + x - v;
        if (i < NN) { g_row[i] = excl; g_cur[i] = excl; }
        __syncthreads();
        if (t == SCAN_BLK - 1) s_carry = base + x;
        __syncthreads();
    }
    if (t == 0) g_row[NN] = ET;
}
__global__ void scatter(const int* __restrict__ ei) {
    int e = blockIdx.x * blockDim.x + threadIdx.x;
    if (e >= ET) return;
    int s, d;
    if (e < NE) { s = ei[e]; d = ei[NE + e]; } else { s = e - NE; d = s; }
    int pos = atomicAdd(&g_cur[d], 1);
    g_csr_src[pos] = s;
}

// ============================================================
// TF32 mma helper
// ============================================================
__device__ __forceinline__ void mma_tf32(float c[4], const unsigned a[4],
                                         const unsigned b[2]) {
    asm volatile(
        "mma.sync.aligned.m16n8k8.row.col.f32.tf32.tf32.f32 "
        "{%0,%1,%2,%3}, {%4,%5,%6,%7}, {%8,%9}, {%0,%1,%2,%3};"
        : "+f"(c[0]), "+f"(c[1]), "+f"(c[2]), "+f"(c[3])
        : "r"(a[0]), "r"(a[1]), "r"(a[2]), "r"(a[3]), "r"(b[0]), "r"(b[1]));
}

// ============================================================
// GEMM1 fused: h1 = x @ W1 (fp16 out) + per-(row,head) att scores.
// M=NN, N=D1=256, K=INC=128. BM=128 BN=64 BK=32, 256 thr.
// Each warp's 32-col tile == one head -> warp-local score reduction.
// ============================================================
__global__ void gemm1_fused(const float* __restrict__ A, const float* __restrict__ B,
                            __half* __restrict__ C,
                            const float* __restrict__ atts,
                            const float* __restrict__ attd,
                            float* __restrict__ as_, float* __restrict__ ad_) {
    const int BM = 128, BN = 64, BK = 32, M = NN, N = D1, K = INC;
    __shared__ unsigned As[BK][BM + 4];
    __shared__ unsigned Bs[BK][BN + 4];

    int t = threadIdx.x, warp = t >> 5, lane = t & 31;
    int wm = warp >> 1, wn = warp & 1;
    int g = lane >> 2, t4 = lane & 3;
    int row0 = blockIdx.y * BM, col0 = blockIdx.x * BN;

    float acc[2][4][4] = {};

    for (int kt = 0; kt < K; kt += BK) {
#pragma unroll
        for (int i = 0; i < 4; i++) {
            int idx = t + i * 256;
            int r = idx >> 3, c4 = (idx & 7) * 4;
            int gr = row0 + r;
            float4 v = (gr < M) ? *(const float4*)&A[(size_t)gr * K + kt + c4]
                                : make_float4(0.f, 0.f, 0.f, 0.f);
            As[c4 + 0][r] = to_tf32(v.x); As[c4 + 1][r] = to_tf32(v.y);
            As[c4 + 2][r] = to_tf32(v.z); As[c4 + 3][r] = to_tf32(v.w);
        }
#pragma unroll
        for (int i = 0; i < 2; i++) {
            int idx = t + i * 256;
            int k = idx >> 4, c4 = (idx & 15) * 4;
            float4 v = *(const float4*)&B[(size_t)(kt + k) * N + col0 + c4];
            Bs[k][c4 + 0] = to_tf32(v.x); Bs[k][c4 + 1] = to_tf32(v.y);
            Bs[k][c4 + 2] = to_tf32(v.z); Bs[k][c4 + 3] = to_tf32(v.w);
        }
        __syncthreads();
#pragma unroll
        for (int k0 = 0; k0 < BK; k0 += 8) {
            unsigned a[2][4], b[4][2];
#pragma unroll
            for (int mi = 0; mi < 2; mi++) {
                int mb = wm * 32 + mi * 16;
                a[mi][0] = As[k0 + t4][mb + g];
                a[mi][1] = As[k0 + t4][mb + 8 + g];
                a[mi][2] = As[k0 + t4 + 4][mb + g];
                a[mi][3] = As[k0 + t4 + 4][mb + 8 + g];
            }
#pragma unroll
            for (int ni = 0; ni < 4; ni++) {
                int nb = wn * 32 + ni * 8;
                b[ni][0] = Bs[k0 + t4][nb + g];
                b[ni][1] = Bs[k0 + t4 + 4][nb + g];
            }
#pragma unroll
            for (int mi = 0; mi < 2; mi++)
#pragma unroll
                for (int ni = 0; ni < 4; ni++)
                    mma_tf32(acc[mi][ni], a[mi], b[ni]);
        }
        __syncthreads();
    }

    // store C (fp16)
#pragma unroll
    for (int mi = 0; mi < 2; mi++)
#pragma unroll
        for (int ni = 0; ni < 4; ni++) {
            int col = col0 + wn * 32 + ni * 8 + t4 * 2;
            int r0 = row0 + wm * 32 + mi * 16 + g, r1 = r0 + 8;
            if (r0 < M)
                *(__half2*)&C[(size_t)r0 * N + col] =
                    __floats2half2_rn(acc[mi][ni][0], acc[mi][ni][1]);
            if (r1 < M)
                *(__half2*)&C[(size_t)r1 * N + col] =
                    __floats2half2_rn(acc[mi][ni][2], acc[mi][ni][3]);
        }

    // fused attention scores: this warp's 32 cols == head hidx
    int hidx = (col0 + wn * 32) >> 5;
    const float* aw = atts + hidx * HID;
    const float* dw = attd + hidx * HID;
#pragma unroll
    for (int mi = 0; mi < 2; mi++) {
        float ss0 = 0.f, dd0 = 0.f, ss1 = 0.f, dd1 = 0.f;
#pragma unroll
        for (int ni = 0; ni < 4; ni++) {
            int c = ni * 8 + t4 * 2;
            float a0 = aw[c], a1 = aw[c + 1];
            float d0 = dw[c], d1 = dw[c + 1];
            ss0 += acc[mi][ni][0] * a0 + acc[mi][ni][1] * a1;
            dd0 += acc[mi][ni][0] * d0 + acc[mi][ni][1] * d1;
            ss1 += acc[mi][ni][2] * a0 + acc[mi][ni][3] * a1;
            dd1 += acc[mi][ni][2] * d0 + acc[mi][ni][3] * d1;
        }
#pragma unroll
        for (int o = 1; o < 4; o <<= 1) {
            ss0 += __shfl_xor_sync(0xffffffffu, ss0, o);
            dd0 += __shfl_xor_sync(0xffffffffu, dd0, o);
            ss1 += __shfl_xor_sync(0xffffffffu, ss1, o);
            dd1 += __shfl_xor_sync(0xffffffffu, dd1, o);
        }
        if (t4 == 0) {
            int r0 = row0 + wm * 32 + mi * 16 + g, r1 = r0 + 8;
            if (r0 < M) { as_[r0 * H1 + hidx] = ss0; ad_[r0 * H1 + hidx] = dd0; }
            if (r1 < M) { as_[r1 * H1 + hidx] = ss1; ad_[r1 * H1 + hidx] = dd1; }
        }
    }
}

// ============================================================
// GEMM2 fused: h2 = out1(fp16) @ W2 (fp16 out) + scores (H=1, C=64).
// M=NN, N=D2=64, K=D1=256. Head spans full block -> smem reduction.
// ============================================================
__global__ void gemm2_fused(const __half* __restrict__ A, const float* __restrict__ B,
                            __half* __restrict__ C,
                            const float* __restrict__ atts,
                            const float* __restrict__ attd,
                            float* __restrict__ as_, float* __restrict__ ad_) {
    const int BM = 128, BN = 64, BK = 32, M = NN, N = D2, K = D1;
    __shared__ unsigned As[BK][BM + 4];
    __shared__ unsigned Bs[BK][BN + 4];
    __shared__ float sS[BM][2], sD[BM][2];

    int t = threadIdx.x, warp = t >> 5, lane = t & 31;
    int wm = warp >> 1, wn = warp & 1;
    int g = lane >> 2, t4 = lane & 3;
    int row0 = blockIdx.y * BM, col0 = 0;

    float acc[2][4][4] = {};

    for (int kt = 0; kt < K; kt += BK) {
        // A: fp16, BM x BK -> 512 uint4(8h) / 256 thr = 2 each
#pragma unroll
        for (int i = 0; i < 2; i++) {
            int idx = t + i * 256;
            int r = idx >> 2, c8 = (idx & 3) * 8;
            int gr = row0 + r;
            uint4 raw = (gr < M) ? *(const uint4*)&A[(size_t)gr * K + kt + c8]
                                 : make_uint4(0, 0, 0, 0);
            const __half2* hp = (const __half2*)&raw;
#pragma unroll
            for (int q = 0; q < 4; q++) {
                float2 f = __half22float2(hp[q]);
                As[c8 + 2 * q][r]     = to_tf32(f.x);
                As[c8 + 2 * q + 1][r] = to_tf32(f.y);
            }
        }
#pragma unroll
        for (int i = 0; i < 2; i++) {
            int idx = t + i * 256;
            int k = idx >> 4, c4 = (idx & 15) * 4;
            float4 v = *(const float4*)&B[(size_t)(kt + k) * N + c4];
            Bs[k][c4 + 0] = to_tf32(v.x); Bs[k][c4 + 1] = to_tf32(v.y);
            Bs[k][c4 + 2] = to_tf32(v.z); Bs[k][c4 + 3] = to_tf32(v.w);
        }
        __syncthreads();
#pragma unroll
        for (int k0 = 0; k0 < BK; k0 += 8) {
            unsigned a[2][4], b[4][2];
#pragma unroll
            for (int mi = 0; mi < 2; mi++) {
                int mb = wm * 32 + mi * 16;
                a[mi][0] = As[k0 + t4][mb + g];
                a[mi][1] = As[k0 + t4][mb + 8 + g];
                a[mi][2] = As[k0 + t4 + 4][mb + g];
                a[mi][3] = As[k0 + t4 + 4][mb + 8 + g];
            }
#pragma unroll
            for (int ni = 0; ni < 4; ni++) {
                int nb = wn * 32 + ni * 8;
                b[ni][0] = Bs[k0 + t4][nb + g];
                b[ni][1] = Bs[k0 + t4 + 4][nb + g];
            }
#pragma unroll
            for (int mi = 0; mi < 2; mi++)
#pragma unroll
                for (int ni = 0; ni < 4; ni++)
                    mma_tf32(acc[mi][ni], a[mi], b[ni]);
        }
        __syncthreads();
    }

#pragma unroll
    for (int mi = 0; mi < 2; mi++)
#pragma unroll
        for (int ni = 0; ni < 4; ni++) {
            int col = wn * 32 + ni * 8 + t4 * 2;
            int r0 = row0 + wm * 32 + mi * 16 + g, r1 = r0 + 8;
            if (r0 < M)
                *(__half2*)&C[(size_t)r0 * N + col] =
                    __floats2half2_rn(acc[mi][ni][0], acc[mi][ni][1]);
            if (r1 < M)
                *(__half2*)&C[(size_t)r1 * N + col] =
                    __floats2half2_rn(acc[mi][ni][2], acc[mi][ni][3]);
        }

    // fused scores across full 64-col head
#pragma unroll
    for (int mi = 0; mi < 2; mi++) {
        float ss0 = 0.f, dd0 = 0.f, ss1 = 0.f, dd1 = 0.f;
#pragma unroll
        for (int ni = 0; ni < 4; ni++) {
            int c = wn * 32 + ni * 8 + t4 * 2;
            float a0 = atts[c], a1 = atts[c + 1];
            float d0 = attd[c], d1 = attd[c + 1];
            ss0 += acc[mi][ni][0] * a0 + acc[mi][ni][1] * a1;
            dd0 += acc[mi][ni][0] * d0 + acc[mi][ni][1] * d1;
            ss1 += acc[mi][ni][2] * a0 + acc[mi][ni][3] * a1;
            dd1 += acc[mi][ni][2] * d0 + acc[mi][ni][3] * d1;
        }
#pragma unroll
        for (int o = 1; o < 4; o <<= 1) {
            ss0 += __shfl_xor_sync(0xffffffffu, ss0, o);
            dd0 += __shfl_xor_sync(0xffffffffu, dd0, o);
            ss1 += __shfl_xor_sync(0xffffffffu, ss1, o);
            dd1 += __shfl_xor_sync(0xffffffffu, dd1, o);
        }
        if (t4 == 0) {
            int lr0 = wm * 32 + mi * 16 + g, lr1 = lr0 + 8;
            sS[lr0][wn] = ss0; sD[lr0][wn] = dd0;
            sS[lr1][wn] = ss1; sD[lr1][wn] = dd1;
        }
    }
    __syncthreads();
    if (t < BM) {
        int gr = row0 + t;
        if (gr < M) {
            as_[gr] = sS[t][0] + sS[t][1];
            ad_[gr] = sD[t][0] + sD[t][1];
        }
    }
}

// ---- layer1: single-pass softmax+aggregation, unrolled x2, fp16 out ----
__global__ void aggr1(const float* __restrict__ b1) {
    int w    = (blockIdx.x * blockDim.x + threadIdx.x) >> 5;
    int lane = threadIdx.x & 31;
    if (w >= NN) return;
    int h8 = lane & 7, head = lane >> 2;

    float adh = g_ad1[w * H1 + h8];
    int beg = g_row[w], end = g_row[w + 1];

    float den = 0.f;
    float acc[8] = {};
    int j = beg;
    for (; j + 1 < end; j += 2) {
        int s0 = g_csr_src[j], s1 = g_csr_src[j + 1];
        float e0 = __expf(lrelu(g_as1[s0 * H1 + h8] + adh));
        float e1 = __expf(lrelu(g_as1[s1 * H1 + h8] + adh));
        den += e0 + e1;
        float x0 = __shfl_sync(0xffffffffu, e0, head);
        float x1 = __shfl_sync(0xffffffffu, e1, head);
        uint4 r0 = *(const uint4*)(g_h1 + (size_t)s0 * D1 + lane * 8);
        uint4 r1 = *(const uint4*)(g_h1 + (size_t)s1 * D1 + lane * 8);
        const __half2* p0 = (const __half2*)&r0;
        const __half2* p1 = (const __half2*)&r1;
#pragma unroll
        for (int q = 0; q < 4; q++) {
            float2 f0 = __half22float2(p0[q]);
            float2 f1 = __half22float2(p1[q]);
            acc[q * 2 + 0] += x0 * f0.x + x1 * f1.x;
            acc[q * 2 + 1] += x0 * f0.y + x1 * f1.y;
        }
    }
    if (j < end) {
        int s0 = g_csr_src[j];
        float e0 = __expf(lrelu(g_as1[s0 * H1 + h8] + adh));
        den += e0;
        float x0 = __shfl_sync(0xffffffffu, e0, head);
        uint4 r0 = *(const uint4*)(g_h1 + (size_t)s0 * D1 + lane * 8);
        const __half2* p0 = (const __half2*)&r0;
#pragma unroll
        for (int q = 0; q < 4; q++) {
            float2 f0 = __half22float2(p0[q]);
            acc[q * 2 + 0] += x0 * f0.x;
            acc[q * 2 + 1] += x0 * f0.y;
        }
    }
    float denh = __shfl_sync(0xffffffffu, den, head);
    float inv  = 1.f / (denh + 1e-16f);
    const float* bb = b1 + lane * 8;
    __half2 o[4];
#pragma unroll
    for (int q = 0; q < 4; q++) {
        float f0 = fmaxf(acc[q * 2 + 0] * inv + bb[q * 2 + 0], 0.f);
        float f1 = fmaxf(acc[q * 2 + 1] * inv + bb[q * 2 + 1], 0.f);
        o[q] = __floats2half2_rn(f0, f1);
    }
    *(uint4*)(g_out1 + (size_t)w * D1 + lane * 8) = *(uint4*)o;
}

// ---- layer2: single-pass; warp per dst node ----
__global__ void aggr2(float* __restrict__ out, const float* __restrict__ b2) {
    int w    = (blockIdx.x * blockDim.x + threadIdx.x) >> 5;
    int lane = threadIdx.x & 31;
    if (w >= NN) return;
    float adh = g_ad2[w];
    int beg = g_row[w], end = g_row[w + 1];

    float den = 0.f;
    float2 acc = {0.f, 0.f};
    int j = beg;
    for (; j + 1 < end; j += 2) {
        int s0 = g_csr_src[j], s1 = g_csr_src[j + 1];
        float e0 = __expf(lrelu(g_as2[s0] + adh));
        float e1 = __expf(lrelu(g_as2[s1] + adh));
        den += e0 + e1;
        float2 f0 = __half22float2(((const __half2*)(g_h2 + (size_t)s0 * D2))[lane]);
        float2 f1 = __half22float2(((const __half2*)(g_h2 + (size_t)s1 * D2))[lane]);
        acc.x += e0 * f0.x + e1 * f1.x;
        acc.y += e0 * f0.y + e1 * f1.y;
    }
    if (j < end) {
        int s0 = g_csr_src[j];
        float e0 = __expf(lrelu(g_as2[s0] + adh));
        den += e0;
        float2 f0 = __half22float2(((const __half2*)(g_h2 + (size_t)s0 * D2))[lane]);
        acc.x += e0 * f0.x;
        acc.y += e0 * f0.y;
    }
    float inv = 1.f / (den + 1e-16f);
    float2 bv = ((const float2*)b2)[lane];
    ((float2*)(out + (size_t)w * D2))[lane] =
        make_float2(acc.x * inv + bv.x, acc.y * inv + bv.y);
}

extern "C" void kernel_launch(void* const* d_in, const int* in_sizes, int n_in,
                              void* d_out, int out_size) {
    const float* x   = (const float*)d_in[0];
    const int*   ei  = (const int*)  d_in[1];
    const float* W1  = (const float*)d_in[2];
    const float* as1 = (const float*)d_in[3];
    const float* ad1 = (const float*)d_in[4];
    const float* b1  = (const float*)d_in[5];
    const float* W2  = (const float*)d_in[6];
    const float* as2 = (const float*)d_in[7];
    const float* ad2 = (const float*)d_in[8];
    const float* b2  = (const float*)d_in[9];
    float* out = (float*)d_out;

    static cudaStream_t s2 = nullptr;
    static cudaEvent_t evFork = nullptr, evJoin = nullptr;
    if (!s2) {
        cudaStreamCreateWithFlags(&s2, cudaStreamNonBlocking);
        cudaEventCreateWithFlags(&evFork, cudaEventDisableTiming);
        cudaEventCreateWithFlags(&evJoin, cudaEventDisableTiming);
    }

    void *p_h1, *p_out1, *p_h2, *p_as1, *p_ad1, *p_as2, *p_ad2;
    cudaGetSymbolAddress(&p_h1,   g_h1);
    cudaGetSymbolAddress(&p_out1, g_out1);
    cudaGetSymbolAddress(&p_h2,   g_h2);
    cudaGetSymbolAddress(&p_as1,  g_as1);
    cudaGetSymbolAddress(&p_ad1,  g_ad1);
    cudaGetSymbolAddress(&p_as2,  g_as2);
    cudaGetSymbolAddress(&p_ad2,  g_ad2);

    // fork: CSR build on s2, concurrent with GEMM1
    cudaEventRecord(evFork, 0);
    cudaStreamWaitEvent(s2, evFork, 0);
    cnt_init<<<(NN + 255) / 256, 256, 0, s2>>>();
    hist<<<(NE + 255) / 256, 256, 0, s2>>>(ei);
    scan_fused<<<1, SCAN_BLK, 0, s2>>>();
    scatter<<<(ET + 255) / 256, 256, 0, s2>>>(ei);
    cudaEventRecord(evJoin, s2);

    // main stream: GEMM1 + fused scores
    {
        dim3 grid(D1 / 64, (NN + 127) / 128);
        gemm1_fused<<<grid, 256>>>(x, W1, (__half*)p_h1, as1, ad1,
                                   (float*)p_as1, (float*)p_ad1);
    }
    cudaStreamWaitEvent(0, evJoin, 0);
    aggr1<<<(NN + 7) / 8, 256>>>(b1);

    {
        dim3 grid(1, (NN + 127) / 128);
        gemm2_fused<<<grid, 256>>>((const __half*)p_out1, W2, (__half*)p_h2,
                                   as2, ad2, (float*)p_as2, (float*)p_ad2);
    }
    aggr2<<<(NN + 7) / 8, 256>>>(out, b2);
}